// round 1
// baseline (speedup 1.0000x reference)
#include <cuda_runtime.h>
#include <math.h>

// ---------------- problem constants ----------------
#define B_    16
#define NTOK  196          // tokens (excl cls) before split
#define SPLN  98           // split_n
#define N_    491          // 1 + 98*4 + 98
#define C_    768
#define HM_   3072
#define H_    12
#define D_    64
#define L_    4
#define M_ROWS (B_*N_)     // 7856

// ---------------- device scratch (globals: allocation-free) ----------------
__device__ float g_x   [B_*N_*C_];      // activations
__device__ float g_h   [B_*N_*C_];      // LN output
__device__ float g_qkv [B_*N_*3*C_];    // qkv
__device__ float g_o   [B_*N_*C_];      // attention output
__device__ float g_mlp [B_*N_*HM_];     // fc1 output
__device__ float g_tok [B_*SPLN*C_];    // gathered top tokens
__device__ int   g_ord [B_*NTOK];
__device__ float g_glb [B_*(N_-1)];
__device__ float g_cls [B_*(N_-1)];

// ---------------- sort: bitonic, descending, stable tie-break ----------------
__global__ void sort_kernel(const float* __restrict__ attn) {
    __shared__ float sv[256];
    __shared__ int   si[256];
    int b = blockIdx.x, t = threadIdx.x;
    sv[t] = (t < NTOK) ? attn[b*NTOK + t] : -INFINITY;
    si[t] = t;
    __syncthreads();
    for (int k = 2; k <= 256; k <<= 1) {
        for (int j = k >> 1; j > 0; j >>= 1) {
            int ix = t ^ j;
            if (ix > t) {
                float v1 = sv[t], v2 = sv[ix];
                int   i1 = si[t], i2 = si[ix];
                // "before" in descending order (stable: idx asc on ties)
                bool before = (v1 > v2) || (v1 == v2 && i1 < i2);
                bool doswap = ((t & k) == 0) ? (!before) : before;
                if (doswap) { sv[t]=v2; sv[ix]=v1; si[t]=i2; si[ix]=i1; }
            }
            __syncthreads();
        }
    }
    if (t < NTOK) g_ord[b*NTOK + t] = si[t];
}

// ---------------- gather: cls + top98 (to g_tok) + tail98 ----------------
__global__ void gather_kernel(const float* __restrict__ xin) {
    int blk = blockIdx.x;          // b*197 + r
    int b = blk / 197, r = blk % 197;
    int t = threadIdx.x;           // 256 threads, 3 elems each
    const float* srow;
    float* drow;
    if (r == 0) {
        srow = xin + (size_t)b*197*C_;
        drow = g_x + (size_t)b*N_*C_;
    } else if (r <= SPLN) {
        int i = r - 1;
        int ord = g_ord[b*NTOK + i];
        srow = xin + ((size_t)b*197 + 1 + ord)*C_;
        drow = g_tok + ((size_t)b*SPLN + i)*C_;
    } else {
        int i = r - 1 - SPLN;
        int ord = g_ord[b*NTOK + SPLN + i];
        srow = xin + ((size_t)b*197 + 1 + ord)*C_;
        drow = g_x + ((size_t)b*N_ + 1 + SPLN*4 + i)*C_;
    }
    drow[t]       = srow[t];
    drow[t + 256] = srow[t + 256];
    drow[t + 512] = srow[t + 512];
}

__global__ void init_kernel() {
    int i = blockIdx.x*blockDim.x + threadIdx.x;
    if (i < B_*(N_-1)) { g_glb[i] = 0.f; g_cls[i] = 0.f; }
}

// ---------------- tiled fp32 GEMM with fused epilogues ----------------
// out = A(MxK) @ W(KxN) + bias, modes:
//   0: bias  1: bias+gelu(erf)  2: bias+residual  3: bias + split row-remap into g_x
#define BKM 16
__global__ __launch_bounds__(256)
void gemm_kernel(const float* __restrict__ A, const float* __restrict__ W,
                 const float* __restrict__ bias, const float* __restrict__ resid,
                 float* __restrict__ out, int M, int N, int K, int mode) {
    __shared__ float As[BKM][64];
    __shared__ float Ws[BKM][64];
    int tid = threadIdx.x;
    int m0 = blockIdx.y * 64, n0 = blockIdx.x * 64;
    int ty = tid >> 4, tx = tid & 15;
    int arow = tid >> 2, akq = tid & 3;
    int wkr = tid >> 4, wcq = tid & 15;
    float acc[4][4] = {};
    for (int kt = 0; kt < K; kt += BKM) {
        float4 af = make_float4(0.f,0.f,0.f,0.f);
        int ga = m0 + arow;
        if (ga < M) af = *(const float4*)(A + (size_t)ga*K + kt + akq*4);
        As[akq*4+0][arow] = af.x;
        As[akq*4+1][arow] = af.y;
        As[akq*4+2][arow] = af.z;
        As[akq*4+3][arow] = af.w;
        float4 wf = *(const float4*)(W + (size_t)(kt + wkr)*N + n0 + wcq*4);
        *(float4*)&Ws[wkr][wcq*4] = wf;
        __syncthreads();
#pragma unroll
        for (int k = 0; k < BKM; k++) {
            float4 a = *(const float4*)&As[k][ty*4];
            float4 w = *(const float4*)&Ws[k][tx*4];
            acc[0][0] += a.x*w.x; acc[0][1] += a.x*w.y; acc[0][2] += a.x*w.z; acc[0][3] += a.x*w.w;
            acc[1][0] += a.y*w.x; acc[1][1] += a.y*w.y; acc[1][2] += a.y*w.z; acc[1][3] += a.y*w.w;
            acc[2][0] += a.z*w.x; acc[2][1] += a.z*w.y; acc[2][2] += a.z*w.z; acc[2][3] += a.z*w.w;
            acc[3][0] += a.w*w.x; acc[3][1] += a.w*w.y; acc[3][2] += a.w*w.z; acc[3][3] += a.w*w.w;
        }
        __syncthreads();
    }
#pragma unroll
    for (int i = 0; i < 4; i++) {
        int row = m0 + ty*4 + i;
        if (row >= M) continue;
        float* orow;
        if (mode == 3) {
            int b = row / SPLN, s = row % SPLN;
            orow = out + ((size_t)b*N_ + 1 + s*4)*C_;   // 3072 contiguous floats
        } else {
            orow = out + (size_t)row*N;
        }
        const float* rrow = (mode == 2) ? (resid + (size_t)row*N) : nullptr;
#pragma unroll
        for (int j = 0; j < 4; j++) {
            int col = n0 + tx*4 + j;
            float v = acc[i][j] + bias[col];
            if (mode == 1)      v = 0.5f * v * (1.0f + erff(v * 0.70710678118654752f));
            else if (mode == 2) v += rrow[col];
            orow[col] = v;
        }
    }
}

// ---------------- layernorm (row per block, C=768, 256 threads) ----------------
__global__ __launch_bounds__(256)
void ln_kernel(const float* __restrict__ in, float* __restrict__ out,
               const float* __restrict__ gamma, const float* __restrict__ beta) {
    int row = blockIdx.x, t = threadIdx.x;
    const float* xr = in + (size_t)row * C_;
    float v0 = xr[t], v1 = xr[t+256], v2 = xr[t+512];
    __shared__ float red[8];
    // mean
    float s = v0 + v1 + v2;
#pragma unroll
    for (int o = 16; o; o >>= 1) s += __shfl_xor_sync(~0u, s, o);
    if ((t & 31) == 0) red[t >> 5] = s;
    __syncthreads();
    float tot = 0.f;
#pragma unroll
    for (int i = 0; i < 8; i++) tot += red[i];
    float mean = tot * (1.0f / C_);
    __syncthreads();
    // var
    float d0 = v0 - mean, d1 = v1 - mean, d2 = v2 - mean;
    float s2 = d0*d0 + d1*d1 + d2*d2;
#pragma unroll
    for (int o = 16; o; o >>= 1) s2 += __shfl_xor_sync(~0u, s2, o);
    if ((t & 31) == 0) red[t >> 5] = s2;
    __syncthreads();
    float tot2 = 0.f;
#pragma unroll
    for (int i = 0; i < 8; i++) tot2 += red[i];
    float inv = rsqrtf(tot2 * (1.0f / C_) + 1e-6f);
    float* orow = out + (size_t)row * C_;
    orow[t]       = d0 * inv * gamma[t]       + beta[t];
    orow[t + 256] = d1 * inv * gamma[t + 256] + beta[t + 256];
    orow[t + 512] = d2 * inv * gamma[t + 512] + beta[t + 512];
}

// ---------------- attention: 8 q-rows / block, full softmax row in smem ----------------
__global__ __launch_bounds__(256)
void attn_kernel(const float* __restrict__ qkv, float* __restrict__ obuf,
                 float* __restrict__ cls_acc) {
    int bh = blockIdx.y;
    int b = bh / H_, h = bh % H_;
    int qbase = blockIdx.x * 8;
    int tid = threadIdx.x, warp = tid >> 5, lane = tid & 31;
    const float* base = qkv + (size_t)b * N_ * (3*C_) + h * D_;

    __shared__ float qs[8][64];
    __shared__ float kv[64][68];
    __shared__ float ss[8][512];

    // load q tile
    for (int idx = tid; idx < 8*64; idx += 256) {
        int r = idx >> 6, c = idx & 63;
        int qr = qbase + r;
        qs[r][c] = (qr < N_) ? base[(size_t)qr*(3*C_) + c] : 0.f;
    }
    int qr = qbase + warp;
    bool rowvalid = (qr < N_);

    // scores: K transposed in smem (kv[d][j])
    for (int kt = 0; kt < 8; kt++) {
        int kb = kt * 64;
        __syncthreads();
        for (int idx = tid; idx < 64*64; idx += 256) {
            int j = idx >> 6, d = idx & 63;
            int krow = kb + j;
            kv[d][j] = (krow < N_) ? base[(size_t)krow*(3*C_) + C_ + d] : 0.f;
        }
        __syncthreads();
        if (rowvalid) {
#pragma unroll
            for (int jj = 0; jj < 2; jj++) {
                int j = lane + jj * 32;
                float s = 0.f;
#pragma unroll 8
                for (int d = 0; d < 64; d++) s += qs[warp][d] * kv[d][j];
                ss[warp][kb + j] = (kb + j < N_) ? s * 0.125f : -INFINITY;
            }
        }
    }
    __syncthreads();

    // softmax (full row in smem), fused cls_attn head-mean
    if (rowvalid) {
        float m = -INFINITY;
        for (int j = lane; j < 512; j += 32) m = fmaxf(m, ss[warp][j]);
#pragma unroll
        for (int o = 16; o; o >>= 1) m = fmaxf(m, __shfl_xor_sync(~0u, m, o));
        float l = 0.f;
        for (int j = lane; j < 512; j += 32) {
            float p = expf(ss[warp][j] - m);   // exp(-inf)=0 for padding
            ss[warp][j] = p;
            l += p;
        }
#pragma unroll
        for (int o = 16; o; o >>= 1) l += __shfl_xor_sync(~0u, l, o);
        float inv = 1.0f / l;
        for (int j = lane; j < 512; j += 32) ss[warp][j] *= inv;
        if (qr == 0) {
            for (int j = 1 + lane; j < N_; j += 32)
                atomicAdd(&cls_acc[b*(N_-1) + (j - 1)], ss[warp][j] * (1.0f / H_));
        }
    }
    __syncthreads();

    // O = P @ V  (V natural layout in smem)
    float o0 = 0.f, o1 = 0.f;
    for (int kt = 0; kt < 8; kt++) {
        int kb = kt * 64;
        __syncthreads();
        for (int idx = tid; idx < 64*64; idx += 256) {
            int j = idx >> 6, d = idx & 63;
            int krow = kb + j;
            kv[j][d] = (krow < N_) ? base[(size_t)krow*(3*C_) + 2*C_ + d] : 0.f;
        }
        __syncthreads();
        if (rowvalid) {
#pragma unroll 16
            for (int j = 0; j < 64; j++) {
                float p = ss[warp][kb + j];
                o0 += p * kv[j][lane];
                o1 += p * kv[j][lane + 32];
            }
        }
    }
    if (rowvalid) {
        float* op = obuf + ((size_t)b*N_ + qr)*C_ + h*D_;
        op[lane]      = o0;
        op[lane + 32] = o1;
    }
}

// ---------------- glb EMA update + cls reset ----------------
__global__ void glb_kernel() {
    int i = blockIdx.x*blockDim.x + threadIdx.x;
    if (i < B_*(N_-1)) {
        g_glb[i] = 0.5f * g_glb[i] + 0.5f * g_cls[i];
        g_cls[i] = 0.f;
    }
}

// ---------------- final output: [x flat][glb flat] ----------------
__global__ void copy_out_kernel(float* __restrict__ out, int out_size) {
    const int NX = B_*N_*C_;
    const int NG = B_*(N_-1);
    for (int i = blockIdx.x*blockDim.x + threadIdx.x; i < out_size;
         i += gridDim.x*blockDim.x) {
        float v = 0.f;
        if (i < NX)            v = g_x[i];
        else if (i < NX + NG)  v = g_glb[i - NX];
        out[i] = v;
    }
}

// ---------------- launch ----------------
extern "C" void kernel_launch(void* const* d_in, const int* in_sizes, int n_in,
                              void* d_out, int out_size) {
    const float* x       = (const float*)d_in[0];
    const float* gattn   = (const float*)d_in[1];
    const float* split_w = (const float*)d_in[2];
    const float* split_b = (const float*)d_in[3];
    const float* ln1_g   = (const float*)d_in[4];
    const float* ln1_b   = (const float*)d_in[5];
    const float* qkv_w   = (const float*)d_in[6];
    const float* qkv_b   = (const float*)d_in[7];
    const float* proj_w  = (const float*)d_in[8];
    const float* proj_b  = (const float*)d_in[9];
    const float* ln2_g   = (const float*)d_in[10];
    const float* ln2_b   = (const float*)d_in[11];
    const float* fc1_w   = (const float*)d_in[12];
    const float* fc1_b   = (const float*)d_in[13];
    const float* fc2_w   = (const float*)d_in[14];
    const float* fc2_b   = (const float*)d_in[15];

    float *px, *ph, *pqkv, *po, *pmlp, *ptok, *pcls;
    cudaGetSymbolAddress((void**)&px,   g_x);
    cudaGetSymbolAddress((void**)&ph,   g_h);
    cudaGetSymbolAddress((void**)&pqkv, g_qkv);
    cudaGetSymbolAddress((void**)&po,   g_o);
    cudaGetSymbolAddress((void**)&pmlp, g_mlp);
    cudaGetSymbolAddress((void**)&ptok, g_tok);
    cudaGetSymbolAddress((void**)&pcls, g_cls);

    // 1) sort + gather + init
    sort_kernel<<<B_, 256>>>(gattn);
    gather_kernel<<<B_*197, 256>>>(x);
    init_kernel<<<(B_*(N_-1) + 255)/256, 256>>>();

    // 2) split GEMM (writes reorganized rows of g_x directly)
    {
        dim3 g(HM_/64 + (4*C_ - HM_)/64, 0); // placeholder avoided below
    }
    {
        int M = B_*SPLN, N = 4*C_, K = C_;
        dim3 grid(N/64, (M + 63)/64);
        gemm_kernel<<<grid, 256>>>(ptok, split_w, split_b, nullptr, px, M, N, K, 3);
    }

    // 3) layers
    for (int l = 0; l < L_; l++) {
        const float* l1g = ln1_g + l*C_;
        const float* l1b = ln1_b + l*C_;
        const float* qw  = qkv_w + (size_t)l*C_*3*C_;
        const float* qb  = qkv_b + l*3*C_;
        const float* pw  = proj_w + (size_t)l*C_*C_;
        const float* pb  = proj_b + l*C_;
        const float* l2g = ln2_g + l*C_;
        const float* l2b = ln2_b + l*C_;
        const float* w1  = fc1_w + (size_t)l*C_*HM_;
        const float* b1  = fc1_b + l*HM_;
        const float* w2  = fc2_w + (size_t)l*HM_*C_;
        const float* b2  = fc2_b + l*C_;

        ln_kernel<<<M_ROWS, 256>>>(px, ph, l1g, l1b);

        { dim3 grid((3*C_)/64, (M_ROWS + 63)/64);
          gemm_kernel<<<grid, 256>>>(ph, qw, qb, nullptr, pqkv, M_ROWS, 3*C_, C_, 0); }

        { dim3 grid((N_ + 7)/8, B_*H_);
          attn_kernel<<<grid, 256>>>(pqkv, po, pcls); }

        glb_kernel<<<(B_*(N_-1) + 255)/256, 256>>>();

        { dim3 grid(C_/64, (M_ROWS + 63)/64);
          gemm_kernel<<<grid, 256>>>(po, pw, pb, px, px, M_ROWS, C_, C_, 2); }

        ln_kernel<<<M_ROWS, 256>>>(px, ph, l2g, l2b);

        { dim3 grid(HM_/64, (M_ROWS + 63)/64);
          gemm_kernel<<<grid, 256>>>(ph, w1, b1, nullptr, pmlp, M_ROWS, HM_, C_, 1); }

        { dim3 grid(C_/64, (M_ROWS + 63)/64);
          gemm_kernel<<<grid, 256>>>(pmlp, w2, b2, px, px, M_ROWS, C_, HM_, 2); }
    }

    // 4) output
    copy_out_kernel<<<2048, 256>>>((float*)d_out, out_size);
}

// round 2
// speedup vs baseline: 1.1299x; 1.1299x over previous
#include <cuda_runtime.h>
#include <math.h>
#include <stdint.h>

// ---------------- problem constants ----------------
#define B_    16
#define NTOK  196
#define SPLN  98
#define N_    491          // 1 + 98*4 + 98
#define C_    768
#define HM_   3072
#define H_    12
#define D_    64
#define L_    4
#define M_ROWS (B_*N_)     // 7856

// ---------------- device scratch ----------------
__device__ float g_x   [B_*N_*C_];
__device__ float g_h   [B_*N_*C_];
__device__ float g_qkv [B_*N_*3*C_];
__device__ float g_o   [B_*N_*C_];
__device__ float g_mlp [B_*N_*HM_];
__device__ float g_tok [B_*SPLN*C_];
__device__ int   g_ord [B_*NTOK];
__device__ float g_glb [B_*(N_-1)];
__device__ float g_cls [B_*(N_-1)];

// ---------------- sort ----------------
__global__ void sort_kernel(const float* __restrict__ attn) {
    __shared__ float sv[256];
    __shared__ int   si[256];
    int b = blockIdx.x, t = threadIdx.x;
    sv[t] = (t < NTOK) ? attn[b*NTOK + t] : -INFINITY;
    si[t] = t;
    __syncthreads();
    for (int k = 2; k <= 256; k <<= 1) {
        for (int j = k >> 1; j > 0; j >>= 1) {
            int ix = t ^ j;
            if (ix > t) {
                float v1 = sv[t], v2 = sv[ix];
                int   i1 = si[t], i2 = si[ix];
                bool before = (v1 > v2) || (v1 == v2 && i1 < i2);
                bool doswap = ((t & k) == 0) ? (!before) : before;
                if (doswap) { sv[t]=v2; sv[ix]=v1; si[t]=i2; si[ix]=i1; }
            }
            __syncthreads();
        }
    }
    if (t < NTOK) g_ord[b*NTOK + t] = si[t];
}

// ---------------- gather ----------------
__global__ void gather_kernel(const float* __restrict__ xin) {
    int blk = blockIdx.x;
    int b = blk / 197, r = blk % 197;
    int t = threadIdx.x;
    const float* srow;
    float* drow;
    if (r == 0) {
        srow = xin + (size_t)b*197*C_;
        drow = g_x + (size_t)b*N_*C_;
    } else if (r <= SPLN) {
        int i = r - 1;
        int ord = g_ord[b*NTOK + i];
        srow = xin + ((size_t)b*197 + 1 + ord)*C_;
        drow = g_tok + ((size_t)b*SPLN + i)*C_;
    } else {
        int i = r - 1 - SPLN;
        int ord = g_ord[b*NTOK + SPLN + i];
        srow = xin + ((size_t)b*197 + 1 + ord)*C_;
        drow = g_x + ((size_t)b*N_ + 1 + SPLN*4 + i)*C_;
    }
    drow[t]       = srow[t];
    drow[t + 256] = srow[t + 256];
    drow[t + 512] = srow[t + 512];
}

__global__ void init_kernel() {
    int i = blockIdx.x*blockDim.x + threadIdx.x;
    if (i < B_*(N_-1)) { g_glb[i] = 0.f; g_cls[i] = 0.f; }
}

// ---------------- tf32 helpers ----------------
__device__ __forceinline__ uint32_t f2tf32(float x) {
    uint32_t r;
    asm("cvt.rna.tf32.f32 %0, %1;" : "=r"(r) : "f"(x));
    return r;
}
__device__ __forceinline__ void mma_tf32(float& c0, float& c1, float& c2, float& c3,
                                         uint32_t a0, uint32_t a1, uint32_t a2, uint32_t a3,
                                         uint32_t b0, uint32_t b1) {
    asm volatile("mma.sync.aligned.m16n8k8.row.col.f32.tf32.tf32.f32 "
                 "{%0,%1,%2,%3}, {%4,%5,%6,%7}, {%8,%9}, {%0,%1,%2,%3};"
                 : "+f"(c0), "+f"(c1), "+f"(c2), "+f"(c3)
                 : "r"(a0), "r"(a1), "r"(a2), "r"(a3), "r"(b0), "r"(b1));
}

// ---------------- tensor-core tf32 GEMM, fused epilogues ----------------
// Block tile 128x128, BK=16, 8 warps (2 M x 4 N), warp tile 64x32.
// modes: 0 bias | 1 bias+gelu(erf) | 2 bias+residual | 3 bias + split row-remap
#define SA 132   // smem row stride (floats): banks = 4*tig + g (perfect permutation)
__global__ __launch_bounds__(256)
void gemm_tc(const float* __restrict__ A, const float* __restrict__ W,
             const float* __restrict__ bias, const float* __restrict__ resid,
             float* __restrict__ out, int M, int N, int K, int mode) {
    __shared__ float As[16*SA];   // [k][m], transposed
    __shared__ float Ws[16*SA];   // [k][n]
    int tid  = threadIdx.x;
    int m0   = blockIdx.y * 128, n0 = blockIdx.x * 128;
    int warp = tid >> 5, lane = tid & 31;
    int g    = lane >> 2, tig = lane & 3;
    int wm0  = (warp >> 2) * 64;      // warp M offset within block
    int wn0  = (warp & 3) * 32;       // warp N offset

    // ldg assignments
    int arow = tid >> 2;              // 0..63 (and +64)
    int acq  = tid & 3;               // A float4 within k-tile
    int wrow = tid >> 4;              // 0..15
    int wcq  = tid & 15;              // W float4 col (and +16)

    float acc[4][4][4];
#pragma unroll
    for (int i = 0; i < 4; i++)
#pragma unroll
        for (int j = 0; j < 4; j++)
#pragma unroll
            for (int c = 0; c < 4; c++) acc[i][j][c] = 0.f;

    float4 ra0, ra1, rw0, rw1;
    const float4 z4 = make_float4(0.f, 0.f, 0.f, 0.f);

    // prologue load kt=0
    {
        int r0 = m0 + arow, r1 = m0 + arow + 64;
        ra0 = (r0 < M) ? *(const float4*)(A + (size_t)r0*K + acq*4) : z4;
        ra1 = (r1 < M) ? *(const float4*)(A + (size_t)r1*K + acq*4) : z4;
        rw0 = *(const float4*)(W + (size_t)wrow*N + n0 + wcq*4);
        rw1 = *(const float4*)(W + (size_t)wrow*N + n0 + (wcq+16)*4);
    }

    for (int kt = 0; kt < K; kt += 16) {
        // store current tile (tf32-rounded)
        {
            int kb = acq * 4;
            As[(kb+0)*SA + arow]      = __uint_as_float(f2tf32(ra0.x));
            As[(kb+1)*SA + arow]      = __uint_as_float(f2tf32(ra0.y));
            As[(kb+2)*SA + arow]      = __uint_as_float(f2tf32(ra0.z));
            As[(kb+3)*SA + arow]      = __uint_as_float(f2tf32(ra0.w));
            As[(kb+0)*SA + arow + 64] = __uint_as_float(f2tf32(ra1.x));
            As[(kb+1)*SA + arow + 64] = __uint_as_float(f2tf32(ra1.y));
            As[(kb+2)*SA + arow + 64] = __uint_as_float(f2tf32(ra1.z));
            As[(kb+3)*SA + arow + 64] = __uint_as_float(f2tf32(ra1.w));
            float* wp0 = &Ws[wrow*SA + wcq*4];
            wp0[0] = __uint_as_float(f2tf32(rw0.x));
            wp0[1] = __uint_as_float(f2tf32(rw0.y));
            wp0[2] = __uint_as_float(f2tf32(rw0.z));
            wp0[3] = __uint_as_float(f2tf32(rw0.w));
            float* wp1 = &Ws[wrow*SA + (wcq+16)*4];
            wp1[0] = __uint_as_float(f2tf32(rw1.x));
            wp1[1] = __uint_as_float(f2tf32(rw1.y));
            wp1[2] = __uint_as_float(f2tf32(rw1.z));
            wp1[3] = __uint_as_float(f2tf32(rw1.w));
        }
        __syncthreads();

        // prefetch next tile into regs (overlaps with mma below)
        if (kt + 16 < K) {
            int r0 = m0 + arow, r1 = m0 + arow + 64;
            int kk = kt + 16;
            ra0 = (r0 < M) ? *(const float4*)(A + (size_t)r0*K + kk + acq*4) : z4;
            ra1 = (r1 < M) ? *(const float4*)(A + (size_t)r1*K + kk + acq*4) : z4;
            rw0 = *(const float4*)(W + (size_t)(kk+wrow)*N + n0 + wcq*4);
            rw1 = *(const float4*)(W + (size_t)(kk+wrow)*N + n0 + (wcq+16)*4);
        }

        // compute 2 k-steps of 8
#pragma unroll
        for (int ks = 0; ks < 2; ks++) {
            int k0 = ks * 8;
            uint32_t a[4][4], b[4][2];
#pragma unroll
            for (int mi = 0; mi < 4; mi++) {
                int mb = wm0 + mi*16 + g;
                a[mi][0] = __float_as_uint(As[(k0+tig)*SA   + mb]);
                a[mi][1] = __float_as_uint(As[(k0+tig)*SA   + mb + 8]);
                a[mi][2] = __float_as_uint(As[(k0+tig+4)*SA + mb]);
                a[mi][3] = __float_as_uint(As[(k0+tig+4)*SA + mb + 8]);
            }
#pragma unroll
            for (int ni = 0; ni < 4; ni++) {
                int nb = wn0 + ni*8 + g;
                b[ni][0] = __float_as_uint(Ws[(k0+tig)*SA   + nb]);
                b[ni][1] = __float_as_uint(Ws[(k0+tig+4)*SA + nb]);
            }
#pragma unroll
            for (int mi = 0; mi < 4; mi++)
#pragma unroll
                for (int ni = 0; ni < 4; ni++)
                    mma_tf32(acc[mi][ni][0], acc[mi][ni][1], acc[mi][ni][2], acc[mi][ni][3],
                             a[mi][0], a[mi][1], a[mi][2], a[mi][3],
                             b[ni][0], b[ni][1]);
        }
        __syncthreads();
    }

    // epilogue
#pragma unroll
    for (int mi = 0; mi < 4; mi++) {
#pragma unroll
        for (int half = 0; half < 2; half++) {
            int row = m0 + wm0 + mi*16 + g + half*8;
            if (row >= M) continue;
            float* orow;
            if (mode == 3) {
                int bb = row / SPLN, s = row % SPLN;
                orow = out + ((size_t)bb*N_ + 1 + (size_t)s*4)*C_;
            } else {
                orow = out + (size_t)row*N;
            }
            const float* rrow = (mode == 2) ? (resid + (size_t)row*N) : nullptr;
#pragma unroll
            for (int ni = 0; ni < 4; ni++) {
                int col = n0 + wn0 + ni*8 + tig*2;
                float v0 = acc[mi][ni][half*2]     + bias[col];
                float v1 = acc[mi][ni][half*2 + 1] + bias[col+1];
                if (mode == 1) {
                    v0 = 0.5f * v0 * (1.0f + erff(v0 * 0.70710678118654752f));
                    v1 = 0.5f * v1 * (1.0f + erff(v1 * 0.70710678118654752f));
                } else if (mode == 2) {
                    v0 += rrow[col];
                    v1 += rrow[col+1];
                }
                *(float2*)(orow + col) = make_float2(v0, v1);
            }
        }
    }
}

// ---------------- layernorm ----------------
__global__ __launch_bounds__(256)
void ln_kernel(const float* __restrict__ in, float* __restrict__ out,
               const float* __restrict__ gamma, const float* __restrict__ beta) {
    int row = blockIdx.x, t = threadIdx.x;
    const float* xr = in + (size_t)row * C_;
    float v0 = xr[t], v1 = xr[t+256], v2 = xr[t+512];
    __shared__ float red[8];
    float s = v0 + v1 + v2;
#pragma unroll
    for (int o = 16; o; o >>= 1) s += __shfl_xor_sync(~0u, s, o);
    if ((t & 31) == 0) red[t >> 5] = s;
    __syncthreads();
    float tot = 0.f;
#pragma unroll
    for (int i = 0; i < 8; i++) tot += red[i];
    float mean = tot * (1.0f / C_);
    __syncthreads();
    float d0 = v0 - mean, d1 = v1 - mean, d2 = v2 - mean;
    float s2 = d0*d0 + d1*d1 + d2*d2;
#pragma unroll
    for (int o = 16; o; o >>= 1) s2 += __shfl_xor_sync(~0u, s2, o);
    if ((t & 31) == 0) red[t >> 5] = s2;
    __syncthreads();
    float tot2 = 0.f;
#pragma unroll
    for (int i = 0; i < 8; i++) tot2 += red[i];
    float inv = rsqrtf(tot2 * (1.0f / C_) + 1e-6f);
    float* orow = out + (size_t)row * C_;
    orow[t]       = d0 * inv * gamma[t]       + beta[t];
    orow[t + 256] = d1 * inv * gamma[t + 256] + beta[t + 256];
    orow[t + 512] = d2 * inv * gamma[t + 512] + beta[t + 512];
}

// ---------------- attention ----------------
__global__ __launch_bounds__(256)
void attn_kernel(const float* __restrict__ qkv, float* __restrict__ obuf,
                 float* __restrict__ cls_acc) {
    int bh = blockIdx.y;
    int b = bh / H_, h = bh % H_;
    int qbase = blockIdx.x * 8;
    int tid = threadIdx.x, warp = tid >> 5, lane = tid & 31;
    const float* base = qkv + (size_t)b * N_ * (3*C_) + h * D_;

    __shared__ float qs[8][64];
    __shared__ float kv[64][68];
    __shared__ float ss[8][512];

    for (int idx = tid; idx < 8*64; idx += 256) {
        int r = idx >> 6, c = idx & 63;
        int qr = qbase + r;
        qs[r][c] = (qr < N_) ? base[(size_t)qr*(3*C_) + c] : 0.f;
    }
    int qr = qbase + warp;
    bool rowvalid = (qr < N_);

    for (int kt = 0; kt < 8; kt++) {
        int kb = kt * 64;
        __syncthreads();
        for (int idx = tid; idx < 64*64; idx += 256) {
            int j = idx >> 6, d = idx & 63;
            int krow = kb + j;
            kv[d][j] = (krow < N_) ? base[(size_t)krow*(3*C_) + C_ + d] : 0.f;
        }
        __syncthreads();
        if (rowvalid) {
#pragma unroll
            for (int jj = 0; jj < 2; jj++) {
                int j = lane + jj * 32;
                float s = 0.f;
#pragma unroll 8
                for (int d = 0; d < 64; d++) s += qs[warp][d] * kv[d][j];
                ss[warp][kb + j] = (kb + j < N_) ? s * 0.125f : -INFINITY;
            }
        }
    }
    __syncthreads();

    if (rowvalid) {
        float m = -INFINITY;
        for (int j = lane; j < 512; j += 32) m = fmaxf(m, ss[warp][j]);
#pragma unroll
        for (int o = 16; o; o >>= 1) m = fmaxf(m, __shfl_xor_sync(~0u, m, o));
        float l = 0.f;
        for (int j = lane; j < 512; j += 32) {
            float p = expf(ss[warp][j] - m);
            ss[warp][j] = p;
            l += p;
        }
#pragma unroll
        for (int o = 16; o; o >>= 1) l += __shfl_xor_sync(~0u, l, o);
        float inv = 1.0f / l;
        for (int j = lane; j < 512; j += 32) ss[warp][j] *= inv;
        if (qr == 0) {
            for (int j = 1 + lane; j < N_; j += 32)
                atomicAdd(&cls_acc[b*(N_-1) + (j - 1)], ss[warp][j] * (1.0f / H_));
        }
    }
    __syncthreads();

    float o0 = 0.f, o1 = 0.f;
    for (int kt = 0; kt < 8; kt++) {
        int kb = kt * 64;
        __syncthreads();
        for (int idx = tid; idx < 64*64; idx += 256) {
            int j = idx >> 6, d = idx & 63;
            int krow = kb + j;
            kv[j][d] = (krow < N_) ? base[(size_t)krow*(3*C_) + 2*C_ + d] : 0.f;
        }
        __syncthreads();
        if (rowvalid) {
#pragma unroll 16
            for (int j = 0; j < 64; j++) {
                float p = ss[warp][kb + j];
                o0 += p * kv[j][lane];
                o1 += p * kv[j][lane + 32];
            }
        }
    }
    if (rowvalid) {
        float* op = obuf + ((size_t)b*N_ + qr)*C_ + h*D_;
        op[lane]      = o0;
        op[lane + 32] = o1;
    }
}

// ---------------- glb EMA ----------------
__global__ void glb_kernel() {
    int i = blockIdx.x*blockDim.x + threadIdx.x;
    if (i < B_*(N_-1)) {
        g_glb[i] = 0.5f * g_glb[i] + 0.5f * g_cls[i];
        g_cls[i] = 0.f;
    }
}

// ---------------- output ----------------
__global__ void copy_out_kernel(float* __restrict__ out, int out_size) {
    const int NX = B_*N_*C_;
    const int NG = B_*(N_-1);
    for (int i = blockIdx.x*blockDim.x + threadIdx.x; i < out_size;
         i += gridDim.x*blockDim.x) {
        float v = 0.f;
        if (i < NX)            v = g_x[i];
        else if (i < NX + NG)  v = g_glb[i - NX];
        out[i] = v;
    }
}

// ---------------- launch ----------------
extern "C" void kernel_launch(void* const* d_in, const int* in_sizes, int n_in,
                              void* d_out, int out_size) {
    const float* x       = (const float*)d_in[0];
    const float* gattn   = (const float*)d_in[1];
    const float* split_w = (const float*)d_in[2];
    const float* split_b = (const float*)d_in[3];
    const float* ln1_g   = (const float*)d_in[4];
    const float* ln1_b   = (const float*)d_in[5];
    const float* qkv_w   = (const float*)d_in[6];
    const float* qkv_b   = (const float*)d_in[7];
    const float* proj_w  = (const float*)d_in[8];
    const float* proj_b  = (const float*)d_in[9];
    const float* ln2_g   = (const float*)d_in[10];
    const float* ln2_b   = (const float*)d_in[11];
    const float* fc1_w   = (const float*)d_in[12];
    const float* fc1_b   = (const float*)d_in[13];
    const float* fc2_w   = (const float*)d_in[14];
    const float* fc2_b   = (const float*)d_in[15];

    float *px, *ph, *pqkv, *po, *pmlp, *ptok, *pcls;
    cudaGetSymbolAddress((void**)&px,   g_x);
    cudaGetSymbolAddress((void**)&ph,   g_h);
    cudaGetSymbolAddress((void**)&pqkv, g_qkv);
    cudaGetSymbolAddress((void**)&po,   g_o);
    cudaGetSymbolAddress((void**)&pmlp, g_mlp);
    cudaGetSymbolAddress((void**)&ptok, g_tok);
    cudaGetSymbolAddress((void**)&pcls, g_cls);

    sort_kernel<<<B_, 256>>>(gattn);
    gather_kernel<<<B_*197, 256>>>(x);
    init_kernel<<<(B_*(N_-1) + 255)/256, 256>>>();

    // split GEMM: M=1568, N=3072, K=768, row-remap epilogue into g_x
    {
        int M = B_*SPLN, N = 4*C_, K = C_;
        dim3 grid(N/128, (M + 127)/128);
        gemm_tc<<<grid, 256>>>(ptok, split_w, split_b, nullptr, px, M, N, K, 3);
    }

    for (int l = 0; l < L_; l++) {
        const float* l1g = ln1_g + l*C_;
        const float* l1b = ln1_b + l*C_;
        const float* qw  = qkv_w + (size_t)l*C_*3*C_;
        const float* qb  = qkv_b + l*3*C_;
        const float* pw  = proj_w + (size_t)l*C_*C_;
        const float* pb  = proj_b + l*C_;
        const float* l2g = ln2_g + l*C_;
        const float* l2b = ln2_b + l*C_;
        const float* w1  = fc1_w + (size_t)l*C_*HM_;
        const float* b1  = fc1_b + l*HM_;
        const float* w2  = fc2_w + (size_t)l*HM_*C_;
        const float* b2  = fc2_b + l*C_;

        ln_kernel<<<M_ROWS, 256>>>(px, ph, l1g, l1b);

        { dim3 grid((3*C_)/128, (M_ROWS + 127)/128);
          gemm_tc<<<grid, 256>>>(ph, qw, qb, nullptr, pqkv, M_ROWS, 3*C_, C_, 0); }

        { dim3 grid((N_ + 7)/8, B_*H_);
          attn_kernel<<<grid, 256>>>(pqkv, po, pcls); }

        glb_kernel<<<(B_*(N_-1) + 255)/256, 256>>>();

        { dim3 grid(C_/128, (M_ROWS + 127)/128);
          gemm_tc<<<grid, 256>>>(po, pw, pb, px, px, M_ROWS, C_, C_, 2); }

        ln_kernel<<<M_ROWS, 256>>>(px, ph, l2g, l2b);

        { dim3 grid(HM_/128, (M_ROWS + 127)/128);
          gemm_tc<<<grid, 256>>>(ph, w1, b1, nullptr, pmlp, M_ROWS, HM_, C_, 1); }

        { dim3 grid(C_/128, (M_ROWS + 127)/128);
          gemm_tc<<<grid, 256>>>(pmlp, w2, b2, px, px, M_ROWS, C_, HM_, 2); }
    }

    copy_out_kernel<<<2048, 256>>>((float*)d_out, out_size);
}

// round 4
// speedup vs baseline: 2.4119x; 2.1345x over previous
#include <cuda_runtime.h>
#include <math.h>
#include <stdint.h>

// ---------------- problem constants ----------------
#define B_    16
#define NTOK  196
#define SPLN  98
#define N_    491          // 1 + 98*4 + 98
#define C_    768
#define HM_   3072
#define H_    12
#define D_    64
#define L_    4
#define M_ROWS (B_*N_)     // 7856

// weight sizes
#define SW_SZ   (C_*4*C_)          // 2359296
#define QW_SZ   (C_*3*C_)          // 1769472
#define PW_SZ   (C_*C_)            // 589824
#define F1_SZ   (C_*HM_)           // 2359296
#define F2_SZ   (HM_*C_)           // 2359296

// ---------------- device scratch ----------------
__device__ float g_x   [B_*N_*C_];
__device__ float g_h   [B_*N_*C_];
__device__ float g_qkv [B_*N_*3*C_];
__device__ float g_o   [B_*N_*C_];
__device__ float g_mlp [B_*N_*HM_];
__device__ float g_tok [B_*SPLN*C_];
__device__ int   g_ord [B_*NTOK];
__device__ float g_glb [B_*(N_-1)];
__device__ float g_cls [B_*(N_-1)];
// tf32-rounded weights
__device__ float g_wsplit[SW_SZ];
__device__ float g_wqkv  [L_*QW_SZ];
__device__ float g_wproj [L_*PW_SZ];
__device__ float g_wfc1  [L_*F1_SZ];
__device__ float g_wfc2  [L_*F2_SZ];

// ---------------- helpers ----------------
__device__ __forceinline__ uint32_t smem_u32(const void* p) {
    uint32_t a;
    asm("{ .reg .u64 t; cvta.to.shared.u64 t, %1; cvt.u32.u64 %0, t; }" : "=r"(a) : "l"(p));
    return a;
}
__device__ __forceinline__ uint32_t f2tf32(float x) {
    uint32_t r;
    asm("cvt.rna.tf32.f32 %0, %1;" : "=r"(r) : "f"(x));
    return r;
}
__device__ __forceinline__ float rndtf32(float x) { return __uint_as_float(f2tf32(x)); }

__device__ __forceinline__ void mma_tf32(float& c0, float& c1, float& c2, float& c3,
                                         uint32_t a0, uint32_t a1, uint32_t a2, uint32_t a3,
                                         uint32_t b0, uint32_t b1) {
    asm volatile("mma.sync.aligned.m16n8k8.row.col.f32.tf32.tf32.f32 "
                 "{%0,%1,%2,%3}, {%4,%5,%6,%7}, {%8,%9}, {%0,%1,%2,%3};"
                 : "+f"(c0), "+f"(c1), "+f"(c2), "+f"(c3)
                 : "r"(a0), "r"(a1), "r"(a2), "r"(a3), "r"(b0), "r"(b1));
}
__device__ __forceinline__ void cp16(uint32_t dst, const float* src, int sz) {
    asm volatile("cp.async.cg.shared.global [%0], [%1], 16, %2;"
                 :: "r"(dst), "l"(src), "r"(sz) : "memory");
}
#define CP_COMMIT() asm volatile("cp.async.commit_group;" ::: "memory")
#define CP_WAIT1()  asm volatile("cp.async.wait_group 1;" ::: "memory")
#define CP_WAIT0()  asm volatile("cp.async.wait_group 0;" ::: "memory")

// ---------------- weight convert ----------------
__global__ void wconv_kernel(const float* __restrict__ src, float* __restrict__ dst, int n) {
    int stride = gridDim.x * blockDim.x;
    for (int i = blockIdx.x*blockDim.x + threadIdx.x; i < n; i += stride)
        dst[i] = rndtf32(src[i]);
}

// ---------------- sort ----------------
__global__ void sort_kernel(const float* __restrict__ attn) {
    __shared__ float sv[256];
    __shared__ int   si[256];
    int b = blockIdx.x, t = threadIdx.x;
    sv[t] = (t < NTOK) ? attn[b*NTOK + t] : -INFINITY;
    si[t] = t;
    __syncthreads();
    for (int k = 2; k <= 256; k <<= 1) {
        for (int j = k >> 1; j > 0; j >>= 1) {
            int ix = t ^ j;
            if (ix > t) {
                float v1 = sv[t], v2 = sv[ix];
                int   i1 = si[t], i2 = si[ix];
                bool before = (v1 > v2) || (v1 == v2 && i1 < i2);
                bool doswap = ((t & k) == 0) ? (!before) : before;
                if (doswap) { sv[t]=v2; sv[ix]=v1; si[t]=i2; si[ix]=i1; }
            }
            __syncthreads();
        }
    }
    if (t < NTOK) g_ord[b*NTOK + t] = si[t];
}

// ---------------- gather (g_tok tf32-rounded: it only feeds the split GEMM) ----------------
__global__ void gather_kernel(const float* __restrict__ xin) {
    int blk = blockIdx.x;
    int b = blk / 197, r = blk % 197;
    int t = threadIdx.x;
    const float* srow;
    float* drow;
    bool rnd = false;
    if (r == 0) {
        srow = xin + (size_t)b*197*C_;
        drow = g_x + (size_t)b*N_*C_;
    } else if (r <= SPLN) {
        int i = r - 1;
        int ord = g_ord[b*NTOK + i];
        srow = xin + ((size_t)b*197 + 1 + ord)*C_;
        drow = g_tok + ((size_t)b*SPLN + i)*C_;
        rnd = true;
    } else {
        int i = r - 1 - SPLN;
        int ord = g_ord[b*NTOK + SPLN + i];
        srow = xin + ((size_t)b*197 + 1 + ord)*C_;
        drow = g_x + ((size_t)b*N_ + 1 + SPLN*4 + i)*C_;
    }
    if (rnd) {
        drow[t]       = rndtf32(srow[t]);
        drow[t + 256] = rndtf32(srow[t + 256]);
        drow[t + 512] = rndtf32(srow[t + 512]);
    } else {
        drow[t]       = srow[t];
        drow[t + 256] = srow[t + 256];
        drow[t + 512] = srow[t + 512];
    }
}

__global__ void init_kernel() {
    int i = blockIdx.x*blockDim.x + threadIdx.x;
    if (i < B_*(N_-1)) { g_glb[i] = 0.f; g_cls[i] = 0.f; }
}

// ---------------- mma.sync tf32 GEMM, 128x128 tile, BK=32, cp.async double buffer ----------------
// Inputs A,W must already be tf32-rounded (bit patterns). Bias/resid fp32.
// modes: 0 bias | 1 bias+gelu(erf), output tf32-rounded | 2 bias+residual | 3 bias + split row-remap
#define A_STRIDE 36
#define W_STRIDE 136
#define A_FL (128*A_STRIDE)        // 4608 floats
#define W_FL (32*W_STRIDE)         // 4352 floats
#define BUF_FL (A_FL + W_FL)       // 8960 floats
#define GEMM_SMEM (2*BUF_FL*4)     // 71680 bytes

__global__ __launch_bounds__(256, 2)
void gemm_cp(const float* __restrict__ A, const float* __restrict__ W,
             const float* __restrict__ bias, const float* __restrict__ resid,
             float* __restrict__ out, int M, int N, int K, int mode) {
    extern __shared__ float sm[];
    int tid  = threadIdx.x;
    int m0   = blockIdx.y * 128, n0 = blockIdx.x * 128;
    int warp = tid >> 5, lane = tid & 31;
    int g    = lane >> 2, tig = lane & 3;
    int wm0  = (warp >> 2) * 64;
    int wn0  = (warp & 3) * 32;

    uint32_t sbase = smem_u32(sm);

    float acc[4][4][4];
#pragma unroll
    for (int i = 0; i < 4; i++)
#pragma unroll
        for (int j = 0; j < 4; j++)
#pragma unroll
            for (int c = 0; c < 4; c++) acc[i][j][c] = 0.f;

    int nt = K >> 5;   // K is a multiple of 32 here (768 or 3072)

    // --- issue macro: copy tile kc into buffer buf ---
#define ISSUE_TILE(kc_, buf_) do {                                           \
        uint32_t ab = sbase + (uint32_t)(buf_) * (BUF_FL*4);                 \
        uint32_t wb = ab + A_FL*4;                                           \
        _Pragma("unroll")                                                    \
        for (int it = 0; it < 4; it++) {                                     \
            int chunk = tid + it*256;                                        \
            int row = chunk >> 3, c4 = chunk & 7;                            \
            int gr = m0 + row;                                               \
            int ok = (gr < M);                                               \
            const float* src = A + (size_t)(ok ? gr : 0)*K + (kc_)*32 + c4*4;\
            cp16(ab + row*(A_STRIDE*4) + c4*16, src, ok ? 16 : 0);           \
        }                                                                    \
        _Pragma("unroll")                                                    \
        for (int it = 0; it < 4; it++) {                                     \
            int chunk = tid + it*256;                                        \
            int kr = chunk >> 5, c4 = chunk & 31;                            \
            const float* src = W + (size_t)((kc_)*32 + kr)*N + n0 + c4*4;    \
            cp16(wb + kr*(W_STRIDE*4) + c4*16, src, 16);                     \
        }                                                                    \
        CP_COMMIT();                                                         \
    } while (0)

    ISSUE_TILE(0, 0);
    ISSUE_TILE(1, 1);

    for (int kc = 0; kc < nt; kc++) {
        int buf = kc & 1;
        if (kc == nt - 1) { CP_WAIT0(); } else { CP_WAIT1(); }
        __syncthreads();

        const float* As = sm + buf * BUF_FL;            // [128][36]
        const float* Ws = sm + buf * BUF_FL + A_FL;     // [32][136]
#pragma unroll
        for (int ks = 0; ks < 4; ks++) {
            int k0 = ks * 8;
            uint32_t a[4][4], b[4][2];
#pragma unroll
            for (int mi = 0; mi < 4; mi++) {
                int mb = wm0 + mi*16 + g;
                a[mi][0] = __float_as_uint(As[mb*A_STRIDE     + k0 + tig]);
                a[mi][1] = __float_as_uint(As[(mb+8)*A_STRIDE + k0 + tig]);
                a[mi][2] = __float_as_uint(As[mb*A_STRIDE     + k0 + tig + 4]);
                a[mi][3] = __float_as_uint(As[(mb+8)*A_STRIDE + k0 + tig + 4]);
            }
#pragma unroll
            for (int ni = 0; ni < 4; ni++) {
                int nb = wn0 + ni*8 + g;
                b[ni][0] = __float_as_uint(Ws[(k0+tig)*W_STRIDE   + nb]);
                b[ni][1] = __float_as_uint(Ws[(k0+tig+4)*W_STRIDE + nb]);
            }
#pragma unroll
            for (int mi = 0; mi < 4; mi++)
#pragma unroll
                for (int ni = 0; ni < 4; ni++)
                    mma_tf32(acc[mi][ni][0], acc[mi][ni][1], acc[mi][ni][2], acc[mi][ni][3],
                             a[mi][0], a[mi][1], a[mi][2], a[mi][3],
                             b[ni][0], b[ni][1]);
        }
        __syncthreads();
        if (kc + 2 < nt) ISSUE_TILE(kc + 2, buf);
    }
#undef ISSUE_TILE

    // epilogue
#pragma unroll
    for (int mi = 0; mi < 4; mi++) {
#pragma unroll
        for (int half = 0; half < 2; half++) {
            int row = m0 + wm0 + mi*16 + g + half*8;
            if (row >= M) continue;
            float* orow;
            if (mode == 3) {
                int bb = row / SPLN, s = row % SPLN;
                orow = out + ((size_t)bb*N_ + 1 + (size_t)s*4)*C_;
            } else {
                orow = out + (size_t)row*N;
            }
            const float* rrow = (mode == 2) ? (resid + (size_t)row*N) : nullptr;
#pragma unroll
            for (int ni = 0; ni < 4; ni++) {
                int col = n0 + wn0 + ni*8 + tig*2;
                float v0 = acc[mi][ni][half*2]     + bias[col];
                float v1 = acc[mi][ni][half*2 + 1] + bias[col+1];
                if (mode == 1) {
                    v0 = 0.5f*v0*(1.0f + erff(v0*0.70710678118654752f));
                    v1 = 0.5f*v1*(1.0f + erff(v1*0.70710678118654752f));
                    v0 = rndtf32(v0);   // g_mlp only feeds fc2 GEMM
                    v1 = rndtf32(v1);
                } else if (mode == 2) {
                    v0 += rrow[col];
                    v1 += rrow[col+1];
                }
                *(float2*)(orow + col) = make_float2(v0, v1);
            }
        }
    }
}

// ---------------- layernorm (output tf32-rounded: h only feeds GEMMs) ----------------
__global__ __launch_bounds__(256)
void ln_kernel(const float* __restrict__ in, float* __restrict__ out,
               const float* __restrict__ gamma, const float* __restrict__ beta) {
    int row = blockIdx.x, t = threadIdx.x;
    const float* xr = in + (size_t)row * C_;
    float v0 = xr[t], v1 = xr[t+256], v2 = xr[t+512];
    __shared__ float red[8];
    float s = v0 + v1 + v2;
#pragma unroll
    for (int o = 16; o; o >>= 1) s += __shfl_xor_sync(~0u, s, o);
    if ((t & 31) == 0) red[t >> 5] = s;
    __syncthreads();
    float tot = 0.f;
#pragma unroll
    for (int i = 0; i < 8; i++) tot += red[i];
    float mean = tot * (1.0f / C_);
    __syncthreads();
    float d0 = v0 - mean, d1 = v1 - mean, d2 = v2 - mean;
    float s2 = d0*d0 + d1*d1 + d2*d2;
#pragma unroll
    for (int o = 16; o; o >>= 1) s2 += __shfl_xor_sync(~0u, s2, o);
    if ((t & 31) == 0) red[t >> 5] = s2;
    __syncthreads();
    float tot2 = 0.f;
#pragma unroll
    for (int i = 0; i < 8; i++) tot2 += red[i];
    float inv = rsqrtf(tot2 * (1.0f / C_) + 1e-6f);
    float* orow = out + (size_t)row * C_;
    orow[t]       = rndtf32(d0 * inv * gamma[t]       + beta[t]);
    orow[t + 256] = rndtf32(d1 * inv * gamma[t + 256] + beta[t + 256]);
    orow[t + 512] = rndtf32(d2 * inv * gamma[t + 512] + beta[t + 512]);
}

// ---------------- attention: 16 q-rows / block (2 per warp), output tf32-rounded ----------------
#define ATTN_SMEM ((16*64 + 64*68 + 16*512)*4)
__global__ __launch_bounds__(256)
void attn_kernel(const float* __restrict__ qkv, float* __restrict__ obuf,
                 float* __restrict__ cls_acc) {
    extern __shared__ float smf[];
    float* qs = smf;                      // [16][64]
    float* kv = smf + 16*64;              // [64][68]
    float* ss = smf + 16*64 + 64*68;      // [16][512]

    int bh = blockIdx.y;
    int b = bh / H_, h = bh % H_;
    int qbase = blockIdx.x * 16;
    int tid = threadIdx.x, warp = tid >> 5, lane = tid & 31;
    const float* base = qkv + (size_t)b * N_ * (3*C_) + h * D_;

    for (int idx = tid; idx < 16*64; idx += 256) {
        int r = idx >> 6, c = idx & 63;
        int qr = qbase + r;
        qs[idx] = (qr < N_) ? base[(size_t)qr*(3*C_) + c] : 0.f;
    }
    int ra = qbase + warp, rb = qbase + warp + 8;
    bool va = ra < N_, vb = rb < N_;

    for (int kt = 0; kt < 8; kt++) {
        int kb = kt * 64;
        __syncthreads();
        for (int idx = tid; idx < 64*64; idx += 256) {
            int j = idx >> 6, d = idx & 63;
            int krow = kb + j;
            kv[d*68 + j] = (krow < N_) ? base[(size_t)krow*(3*C_) + C_ + d] : 0.f;
        }
        __syncthreads();
#pragma unroll
        for (int jj = 0; jj < 2; jj++) {
            int j = lane + jj * 32;
            float sa = 0.f, sb = 0.f;
#pragma unroll 8
            for (int d = 0; d < 64; d++) {
                float kvv = kv[d*68 + j];
                sa += qs[warp*64 + d]     * kvv;
                sb += qs[(warp+8)*64 + d] * kvv;
            }
            bool inr = (kb + j) < N_;
            if (va) ss[warp*512     + kb + j] = inr ? sa * 0.125f : -INFINITY;
            if (vb) ss[(warp+8)*512 + kb + j] = inr ? sb * 0.125f : -INFINITY;
        }
    }
    __syncthreads();

#pragma unroll
    for (int rr = 0; rr < 2; rr++) {
        int sr = warp + rr*8;
        int qr = qbase + sr;
        if (qr >= N_) continue;
        float* row = ss + sr*512;
        float m = -INFINITY;
        for (int j = lane; j < 512; j += 32) m = fmaxf(m, row[j]);
#pragma unroll
        for (int o = 16; o; o >>= 1) m = fmaxf(m, __shfl_xor_sync(~0u, m, o));
        float l = 0.f;
        for (int j = lane; j < 512; j += 32) {
            float p = expf(row[j] - m);
            row[j] = p;
            l += p;
        }
#pragma unroll
        for (int o = 16; o; o >>= 1) l += __shfl_xor_sync(~0u, l, o);
        float inv = 1.0f / l;
        for (int j = lane; j < 512; j += 32) row[j] *= inv;
        if (qr == 0) {
            for (int j = 1 + lane; j < N_; j += 32)
                atomicAdd(&cls_acc[b*(N_-1) + (j - 1)], row[j] * (1.0f / H_));
        }
    }
    __syncthreads();

    float oa0 = 0.f, oa1 = 0.f, ob0 = 0.f, ob1 = 0.f;
    for (int kt = 0; kt < 8; kt++) {
        int kb = kt * 64;
        __syncthreads();
        for (int idx = tid; idx < 64*64; idx += 256) {
            int j = idx >> 6, d = idx & 63;
            int krow = kb + j;
            kv[j*68 + d] = (krow < N_) ? base[(size_t)krow*(3*C_) + 2*C_ + d] : 0.f;
        }
        __syncthreads();
        if (va) {
#pragma unroll 16
            for (int j = 0; j < 64; j++) {
                float pa = ss[warp*512 + kb + j];
                float pb = vb ? ss[(warp+8)*512 + kb + j] : 0.f;
                float v0 = kv[j*68 + lane], v1 = kv[j*68 + lane + 32];
                oa0 += pa*v0; oa1 += pa*v1;
                ob0 += pb*v0; ob1 += pb*v1;
            }
        }
    }
    if (va) {
        float* op = obuf + ((size_t)b*N_ + ra)*C_ + h*D_;
        op[lane]      = rndtf32(oa0);
        op[lane + 32] = rndtf32(oa1);
    }
    if (vb) {
        float* op = obuf + ((size_t)b*N_ + rb)*C_ + h*D_;
        op[lane]      = rndtf32(ob0);
        op[lane + 32] = rndtf32(ob1);
    }
}

// ---------------- glb EMA ----------------
__global__ void glb_kernel() {
    int i = blockIdx.x*blockDim.x + threadIdx.x;
    if (i < B_*(N_-1)) {
        g_glb[i] = 0.5f * g_glb[i] + 0.5f * g_cls[i];
        g_cls[i] = 0.f;
    }
}

// ---------------- output ----------------
__global__ void copy_out_kernel(float* __restrict__ out, int out_size) {
    const int NX = B_*N_*C_;
    const int NG = B_*(N_-1);
    for (int i = blockIdx.x*blockDim.x + threadIdx.x; i < out_size;
         i += gridDim.x*blockDim.x) {
        float v = 0.f;
        if (i < NX)            v = g_x[i];
        else if (i < NX + NG)  v = g_glb[i - NX];
        out[i] = v;
    }
}

// ---------------- launch ----------------
extern "C" void kernel_launch(void* const* d_in, const int* in_sizes, int n_in,
                              void* d_out, int out_size) {
    const float* x       = (const float*)d_in[0];
    const float* gattn   = (const float*)d_in[1];
    const float* split_w = (const float*)d_in[2];
    const float* split_b = (const float*)d_in[3];
    const float* ln1_g   = (const float*)d_in[4];
    const float* ln1_b   = (const float*)d_in[5];
    const float* qkv_w   = (const float*)d_in[6];
    const float* qkv_b   = (const float*)d_in[7];
    const float* proj_w  = (const float*)d_in[8];
    const float* proj_b  = (const float*)d_in[9];
    const float* ln2_g   = (const float*)d_in[10];
    const float* ln2_b   = (const float*)d_in[11];
    const float* fc1_w   = (const float*)d_in[12];
    const float* fc1_b   = (const float*)d_in[13];
    const float* fc2_w   = (const float*)d_in[14];
    const float* fc2_b   = (const float*)d_in[15];

    float *px, *ph, *pqkv, *po, *pmlp, *ptok, *pcls;
    float *pwsplit, *pwqkv, *pwproj, *pwfc1, *pwfc2;
    cudaGetSymbolAddress((void**)&px,   g_x);
    cudaGetSymbolAddress((void**)&ph,   g_h);
    cudaGetSymbolAddress((void**)&pqkv, g_qkv);
    cudaGetSymbolAddress((void**)&po,   g_o);
    cudaGetSymbolAddress((void**)&pmlp, g_mlp);
    cudaGetSymbolAddress((void**)&ptok, g_tok);
    cudaGetSymbolAddress((void**)&pcls, g_cls);
    cudaGetSymbolAddress((void**)&pwsplit, g_wsplit);
    cudaGetSymbolAddress((void**)&pwqkv,   g_wqkv);
    cudaGetSymbolAddress((void**)&pwproj,  g_wproj);
    cudaGetSymbolAddress((void**)&pwfc1,   g_wfc1);
    cudaGetSymbolAddress((void**)&pwfc2,   g_wfc2);

    cudaFuncSetAttribute(gemm_cp,     cudaFuncAttributeMaxDynamicSharedMemorySize, GEMM_SMEM);
    cudaFuncSetAttribute(attn_kernel, cudaFuncAttributeMaxDynamicSharedMemorySize, ATTN_SMEM);

    // weight conversion (tf32 rna, once per launch)
    wconv_kernel<<<2048, 256>>>(split_w, pwsplit, SW_SZ);
    wconv_kernel<<<2048, 256>>>(qkv_w,   pwqkv,   L_*QW_SZ);
    wconv_kernel<<<2048, 256>>>(proj_w,  pwproj,  L_*PW_SZ);
    wconv_kernel<<<2048, 256>>>(fc1_w,   pwfc1,   L_*F1_SZ);
    wconv_kernel<<<2048, 256>>>(fc2_w,   pwfc2,   L_*F2_SZ);

    sort_kernel<<<B_, 256>>>(gattn);
    gather_kernel<<<B_*197, 256>>>(x);
    init_kernel<<<(B_*(N_-1) + 255)/256, 256>>>();

    // split GEMM: M=1568, N=3072, K=768, row-remap epilogue into g_x
    {
        int M = B_*SPLN, N = 4*C_, K = C_;
        dim3 grid(N/128, (M + 127)/128);
        gemm_cp<<<grid, 256, GEMM_SMEM>>>(ptok, pwsplit, split_b, nullptr, px, M, N, K, 3);
    }

    for (int l = 0; l < L_; l++) {
        const float* l1g = ln1_g + l*C_;
        const float* l1b = ln1_b + l*C_;
        const float* qw  = pwqkv + (size_t)l*QW_SZ;
        const float* qb  = qkv_b + l*3*C_;
        const float* pw  = pwproj + (size_t)l*PW_SZ;
        const float* pb  = proj_b + l*C_;
        const float* l2g = ln2_g + l*C_;
        const float* l2b = ln2_b + l*C_;
        const float* w1  = pwfc1 + (size_t)l*F1_SZ;
        const float* b1  = fc1_b + l*HM_;
        const float* w2  = pwfc2 + (size_t)l*F2_SZ;
        const float* b2  = fc2_b + l*C_;

        ln_kernel<<<M_ROWS, 256>>>(px, ph, l1g, l1b);

        { dim3 grid((3*C_)/128, (M_ROWS + 127)/128);
          gemm_cp<<<grid, 256, GEMM_SMEM>>>(ph, qw, qb, nullptr, pqkv, M_ROWS, 3*C_, C_, 0); }

        { dim3 grid((N_ + 15)/16, B_*H_);
          attn_kernel<<<grid, 256, ATTN_SMEM>>>(pqkv, po, pcls); }

        glb_kernel<<<(B_*(N_-1) + 255)/256, 256>>>();

        { dim3 grid(C_/128, (M_ROWS + 127)/128);
          gemm_cp<<<grid, 256, GEMM_SMEM>>>(po, pw, pb, px, px, M_ROWS, C_, C_, 2); }

        ln_kernel<<<M_ROWS, 256>>>(px, ph, l2g, l2b);

        { dim3 grid(HM_/128, (M_ROWS + 127)/128);
          gemm_cp<<<grid, 256, GEMM_SMEM>>>(ph, w1, b1, nullptr, pmlp, M_ROWS, HM_, C_, 1); }

        { dim3 grid(C_/128, (M_ROWS + 127)/128);
          gemm_cp<<<grid, 256, GEMM_SMEM>>>(pmlp, w2, b2, px, px, M_ROWS, C_, HM_, 2); }
    }

    copy_out_kernel<<<2048, 256>>>((float*)d_out, out_size);
}

// round 5
// speedup vs baseline: 4.4526x; 1.8461x over previous
#include <cuda_runtime.h>
#include <math.h>
#include <stdint.h>

// ---------------- problem constants ----------------
#define B_    16
#define NTOK  196
#define SPLN  98
#define N_    491          // 1 + 98*4 + 98
#define C_    768
#define HM_   3072
#define H_    12
#define D_    64
#define L_    4
#define M_ROWS (B_*N_)     // 7856

// weight sizes
#define SW_SZ   (C_*4*C_)
#define QW_SZ   (C_*3*C_)
#define PW_SZ   (C_*C_)
#define F1_SZ   (C_*HM_)
#define F2_SZ   (HM_*C_)

// ---------------- device scratch ----------------
__device__ float g_x   [B_*N_*C_];
__device__ float g_h   [B_*N_*C_];
__device__ float g_qkv [B_*N_*3*C_];
__device__ float g_o   [B_*N_*C_];
__device__ float g_mlp [B_*N_*HM_];
__device__ float g_tok [B_*SPLN*C_];
__device__ int   g_ord [B_*NTOK];
__device__ float g_glb [B_*(N_-1)];
__device__ float g_cls [B_*(N_-1)];
// tf32-rounded weights
__device__ float g_wsplit[SW_SZ];
__device__ float g_wqkv  [L_*QW_SZ];
__device__ float g_wproj [L_*PW_SZ];
__device__ float g_wfc1  [L_*F1_SZ];
__device__ float g_wfc2  [L_*F2_SZ];

// ---------------- helpers ----------------
__device__ __forceinline__ uint32_t smem_u32(const void* p) {
    uint32_t a;
    asm("{ .reg .u64 t; cvta.to.shared.u64 t, %1; cvt.u32.u64 %0, t; }" : "=r"(a) : "l"(p));
    return a;
}
__device__ __forceinline__ uint32_t f2tf32(float x) {
    uint32_t r;
    asm("cvt.rna.tf32.f32 %0, %1;" : "=r"(r) : "f"(x));
    return r;
}
__device__ __forceinline__ float rndtf32(float x) { return __uint_as_float(f2tf32(x)); }

__device__ __forceinline__ void mma_tf32(float& c0, float& c1, float& c2, float& c3,
                                         uint32_t a0, uint32_t a1, uint32_t a2, uint32_t a3,
                                         uint32_t b0, uint32_t b1) {
    asm volatile("mma.sync.aligned.m16n8k8.row.col.f32.tf32.tf32.f32 "
                 "{%0,%1,%2,%3}, {%4,%5,%6,%7}, {%8,%9}, {%0,%1,%2,%3};"
                 : "+f"(c0), "+f"(c1), "+f"(c2), "+f"(c3)
                 : "r"(a0), "r"(a1), "r"(a2), "r"(a3), "r"(b0), "r"(b1));
}
__device__ __forceinline__ void cp16(uint32_t dst, const float* src, int sz) {
    asm volatile("cp.async.cg.shared.global [%0], [%1], 16, %2;"
                 :: "r"(dst), "l"(src), "r"(sz) : "memory");
}
#define CP_COMMIT() asm volatile("cp.async.commit_group;" ::: "memory")
#define CP_WAIT1()  asm volatile("cp.async.wait_group 1;" ::: "memory")
#define CP_WAIT0()  asm volatile("cp.async.wait_group 0;" ::: "memory")

// ---------------- weight convert ----------------
__global__ void wconv_kernel(const float* __restrict__ src, float* __restrict__ dst, int n) {
    int stride = gridDim.x * blockDim.x;
    for (int i = blockIdx.x*blockDim.x + threadIdx.x; i < n; i += stride)
        dst[i] = rndtf32(src[i]);
}

// ---------------- sort ----------------
__global__ void sort_kernel(const float* __restrict__ attn) {
    __shared__ float sv[256];
    __shared__ int   si[256];
    int b = blockIdx.x, t = threadIdx.x;
    sv[t] = (t < NTOK) ? attn[b*NTOK + t] : -INFINITY;
    si[t] = t;
    __syncthreads();
    for (int k = 2; k <= 256; k <<= 1) {
        for (int j = k >> 1; j > 0; j >>= 1) {
            int ix = t ^ j;
            if (ix > t) {
                float v1 = sv[t], v2 = sv[ix];
                int   i1 = si[t], i2 = si[ix];
                bool before = (v1 > v2) || (v1 == v2 && i1 < i2);
                bool doswap = ((t & k) == 0) ? (!before) : before;
                if (doswap) { sv[t]=v2; sv[ix]=v1; si[t]=i2; si[ix]=i1; }
            }
            __syncthreads();
        }
    }
    if (t < NTOK) g_ord[b*NTOK + t] = si[t];
}

// ---------------- gather ----------------
__global__ void gather_kernel(const float* __restrict__ xin) {
    int blk = blockIdx.x;
    int b = blk / 197, r = blk % 197;
    int t = threadIdx.x;
    const float* srow;
    float* drow;
    bool rnd = false;
    if (r == 0) {
        srow = xin + (size_t)b*197*C_;
        drow = g_x + (size_t)b*N_*C_;
    } else if (r <= SPLN) {
        int i = r - 1;
        int ord = g_ord[b*NTOK + i];
        srow = xin + ((size_t)b*197 + 1 + ord)*C_;
        drow = g_tok + ((size_t)b*SPLN + i)*C_;
        rnd = true;
    } else {
        int i = r - 1 - SPLN;
        int ord = g_ord[b*NTOK + SPLN + i];
        srow = xin + ((size_t)b*197 + 1 + ord)*C_;
        drow = g_x + ((size_t)b*N_ + 1 + SPLN*4 + i)*C_;
    }
    if (rnd) {
        drow[t]       = rndtf32(srow[t]);
        drow[t + 256] = rndtf32(srow[t + 256]);
        drow[t + 512] = rndtf32(srow[t + 512]);
    } else {
        drow[t]       = srow[t];
        drow[t + 256] = srow[t + 256];
        drow[t + 512] = srow[t + 512];
    }
}

__global__ void init_kernel() {
    int i = blockIdx.x*blockDim.x + threadIdx.x;
    if (i < B_*(N_-1)) { g_glb[i] = 0.f; g_cls[i] = 0.f; }
}

// ---------------- mma.sync tf32 GEMM, 128x128 tile, BK=32, cp.async double buffer ----------------
#define A_STRIDE 36
#define W_STRIDE 136
#define A_FL (128*A_STRIDE)
#define W_FL (32*W_STRIDE)
#define BUF_FL (A_FL + W_FL)
#define GEMM_SMEM (2*BUF_FL*4)

__global__ __launch_bounds__(256, 2)
void gemm_cp(const float* __restrict__ A, const float* __restrict__ W,
             const float* __restrict__ bias, const float* __restrict__ resid,
             float* __restrict__ out, int M, int N, int K, int mode) {
    extern __shared__ float sm[];
    int tid  = threadIdx.x;
    int m0   = blockIdx.y * 128, n0 = blockIdx.x * 128;
    int warp = tid >> 5, lane = tid & 31;
    int g    = lane >> 2, tig = lane & 3;
    int wm0  = (warp >> 2) * 64;
    int wn0  = (warp & 3) * 32;

    uint32_t sbase = smem_u32(sm);

    float acc[4][4][4];
#pragma unroll
    for (int i = 0; i < 4; i++)
#pragma unroll
        for (int j = 0; j < 4; j++)
#pragma unroll
            for (int c = 0; c < 4; c++) acc[i][j][c] = 0.f;

    int nt = K >> 5;

#define ISSUE_TILE(kc_, buf_) do {                                           \
        uint32_t ab = sbase + (uint32_t)(buf_) * (BUF_FL*4);                 \
        uint32_t wb = ab + A_FL*4;                                           \
        _Pragma("unroll")                                                    \
        for (int it = 0; it < 4; it++) {                                     \
            int chunk = tid + it*256;                                        \
            int row = chunk >> 3, c4 = chunk & 7;                            \
            int gr = m0 + row;                                               \
            int ok = (gr < M);                                               \
            const float* src = A + (size_t)(ok ? gr : 0)*K + (kc_)*32 + c4*4;\
            cp16(ab + row*(A_STRIDE*4) + c4*16, src, ok ? 16 : 0);           \
        }                                                                    \
        _Pragma("unroll")                                                    \
        for (int it = 0; it < 4; it++) {                                     \
            int chunk = tid + it*256;                                        \
            int kr = chunk >> 5, c4 = chunk & 31;                            \
            const float* src = W + (size_t)((kc_)*32 + kr)*N + n0 + c4*4;    \
            cp16(wb + kr*(W_STRIDE*4) + c4*16, src, 16);                     \
        }                                                                    \
        CP_COMMIT();                                                         \
    } while (0)

    ISSUE_TILE(0, 0);
    ISSUE_TILE(1, 1);

    for (int kc = 0; kc < nt; kc++) {
        int buf = kc & 1;
        if (kc == nt - 1) { CP_WAIT0(); } else { CP_WAIT1(); }
        __syncthreads();

        const float* As = sm + buf * BUF_FL;
        const float* Ws = sm + buf * BUF_FL + A_FL;
#pragma unroll
        for (int ks = 0; ks < 4; ks++) {
            int k0 = ks * 8;
            uint32_t a[4][4], b[4][2];
#pragma unroll
            for (int mi = 0; mi < 4; mi++) {
                int mb = wm0 + mi*16 + g;
                a[mi][0] = __float_as_uint(As[mb*A_STRIDE     + k0 + tig]);
                a[mi][1] = __float_as_uint(As[(mb+8)*A_STRIDE + k0 + tig]);
                a[mi][2] = __float_as_uint(As[mb*A_STRIDE     + k0 + tig + 4]);
                a[mi][3] = __float_as_uint(As[(mb+8)*A_STRIDE + k0 + tig + 4]);
            }
#pragma unroll
            for (int ni = 0; ni < 4; ni++) {
                int nb = wn0 + ni*8 + g;
                b[ni][0] = __float_as_uint(Ws[(k0+tig)*W_STRIDE   + nb]);
                b[ni][1] = __float_as_uint(Ws[(k0+tig+4)*W_STRIDE + nb]);
            }
#pragma unroll
            for (int mi = 0; mi < 4; mi++)
#pragma unroll
                for (int ni = 0; ni < 4; ni++)
                    mma_tf32(acc[mi][ni][0], acc[mi][ni][1], acc[mi][ni][2], acc[mi][ni][3],
                             a[mi][0], a[mi][1], a[mi][2], a[mi][3],
                             b[ni][0], b[ni][1]);
        }
        __syncthreads();
        if (kc + 2 < nt) ISSUE_TILE(kc + 2, buf);
    }
#undef ISSUE_TILE

#pragma unroll
    for (int mi = 0; mi < 4; mi++) {
#pragma unroll
        for (int half = 0; half < 2; half++) {
            int row = m0 + wm0 + mi*16 + g + half*8;
            if (row >= M) continue;
            float* orow;
            if (mode == 3) {
                int bb = row / SPLN, s = row % SPLN;
                orow = out + ((size_t)bb*N_ + 1 + (size_t)s*4)*C_;
            } else {
                orow = out + (size_t)row*N;
            }
            const float* rrow = (mode == 2) ? (resid + (size_t)row*N) : nullptr;
#pragma unroll
            for (int ni = 0; ni < 4; ni++) {
                int col = n0 + wn0 + ni*8 + tig*2;
                float v0 = acc[mi][ni][half*2]     + bias[col];
                float v1 = acc[mi][ni][half*2 + 1] + bias[col+1];
                if (mode == 1) {
                    v0 = 0.5f*v0*(1.0f + erff(v0*0.70710678118654752f));
                    v1 = 0.5f*v1*(1.0f + erff(v1*0.70710678118654752f));
                    v0 = rndtf32(v0);
                    v1 = rndtf32(v1);
                } else if (mode == 2) {
                    v0 += rrow[col];
                    v1 += rrow[col+1];
                }
                *(float2*)(orow + col) = make_float2(v0, v1);
            }
        }
    }
}

// ---------------- layernorm (tf32-rounded output) ----------------
__global__ __launch_bounds__(256)
void ln_kernel(const float* __restrict__ in, float* __restrict__ out,
               const float* __restrict__ gamma, const float* __restrict__ beta) {
    int row = blockIdx.x, t = threadIdx.x;
    const float* xr = in + (size_t)row * C_;
    float v0 = xr[t], v1 = xr[t+256], v2 = xr[t+512];
    __shared__ float red[8];
    float s = v0 + v1 + v2;
#pragma unroll
    for (int o = 16; o; o >>= 1) s += __shfl_xor_sync(~0u, s, o);
    if ((t & 31) == 0) red[t >> 5] = s;
    __syncthreads();
    float tot = 0.f;
#pragma unroll
    for (int i = 0; i < 8; i++) tot += red[i];
    float mean = tot * (1.0f / C_);
    __syncthreads();
    float d0 = v0 - mean, d1 = v1 - mean, d2 = v2 - mean;
    float s2 = d0*d0 + d1*d1 + d2*d2;
#pragma unroll
    for (int o = 16; o; o >>= 1) s2 += __shfl_xor_sync(~0u, s2, o);
    if ((t & 31) == 0) red[t >> 5] = s2;
    __syncthreads();
    float tot2 = 0.f;
#pragma unroll
    for (int i = 0; i < 8; i++) tot2 += red[i];
    float inv = rsqrtf(tot2 * (1.0f / C_) + 1e-6f);
    float* orow = out + (size_t)row * C_;
    orow[t]       = rndtf32(d0 * inv * gamma[t]       + beta[t]);
    orow[t + 256] = rndtf32(d1 * inv * gamma[t + 256] + beta[t + 256]);
    orow[t + 512] = rndtf32(d2 * inv * gamma[t + 512] + beta[t + 512]);
}

// ---------------- flash attention (tf32 mma), 128 q-rows per CTA ----------------
// smem floats: Q [128][68] @0 ; K 2x[64][68] @8704 ; V 2x[64][72] @17408 ; P [128][68] @26624
#define FA_SMEM 141312
__global__ __launch_bounds__(256)
void flash_attn(const float* __restrict__ qkv, float* __restrict__ obuf) {
    extern __shared__ float sf[];
    float* Qs  = sf;
    float* KsB = sf + 8704;
    float* VsB = sf + 17408;
    float* Ps  = sf + 26624;

    int bh = blockIdx.y;
    int b = bh / H_, h = bh % H_;
    int q0 = blockIdx.x * 128;
    int tid = threadIdx.x, warp = tid >> 5, lane = tid & 31;
    int g = lane >> 2, tig = lane & 3;
    const float* base = qkv + (size_t)b * N_ * (3*C_) + h * D_;
    uint32_t sb = smem_u32(sf);

    // Q tile (rna-rounded)
    for (int idx = tid; idx < 128*16; idx += 256) {
        int r = idx >> 4, c4 = idx & 15;
        int qr = q0 + r;
        float4 f = make_float4(0.f,0.f,0.f,0.f);
        if (qr < N_) f = *(const float4*)(base + (size_t)qr*(3*C_) + c4*4);
        float* dst = Qs + r*68 + c4*4;
        dst[0]=rndtf32(f.x); dst[1]=rndtf32(f.y); dst[2]=rndtf32(f.z); dst[3]=rndtf32(f.w);
    }

#define FA_ISSUE(kt_, buf_) do {                                              \
        uint32_t kb8 = sb + (uint32_t)(8704 + (buf_)*4352)*4u;                \
        uint32_t vb8 = sb + (uint32_t)(17408 + (buf_)*4608)*4u;               \
        _Pragma("unroll")                                                     \
        for (int it = 0; it < 4; it++) {                                      \
            int chunk = tid + it*256;                                         \
            int r = chunk >> 4, c4 = chunk & 15;                              \
            int kr = (kt_)*64 + r;                                            \
            int ok = (kr < N_);                                               \
            const float* ksrc = base + (size_t)(ok ? kr : 0)*(3*C_) + C_   + c4*4; \
            const float* vsrc = base + (size_t)(ok ? kr : 0)*(3*C_) + 2*C_ + c4*4; \
            cp16(kb8 + (uint32_t)(r*68 + c4*4)*4u, ksrc, ok ? 16 : 0);        \
            cp16(vb8 + (uint32_t)(r*72 + c4*4)*4u, vsrc, ok ? 16 : 0);        \
        }                                                                     \
        CP_COMMIT();                                                          \
    } while (0)

    FA_ISSUE(0, 0);
    FA_ISSUE(1, 1);

    float o[8][4];
#pragma unroll
    for (int i = 0; i < 8; i++) { o[i][0]=0.f; o[i][1]=0.f; o[i][2]=0.f; o[i][3]=0.f; }
    float mr0 = -INFINITY, mr1 = -INFINITY, l0 = 0.f, l1 = 0.f;

    float* Pw = Ps + warp*16*68;
    const float* Qw = Qs + warp*16*68;

    for (int kt = 0; kt < 8; kt++) {
        int buf = kt & 1;
        if (kt == 7) { CP_WAIT0(); } else { CP_WAIT1(); }
        __syncthreads();
        const float* Kt = KsB + buf*4352;
        const float* Vt = VsB + buf*4608;

        // S = Q K^T (warp computes 16x64)
        float s[8][4];
#pragma unroll
        for (int i = 0; i < 8; i++) { s[i][0]=0.f; s[i][1]=0.f; s[i][2]=0.f; s[i][3]=0.f; }
#pragma unroll
        for (int ks = 0; ks < 8; ks++) {
            int k0 = ks*8;
            uint32_t a0 = __float_as_uint(Qw[g*68     + k0 + tig]);
            uint32_t a1 = __float_as_uint(Qw[(g+8)*68 + k0 + tig]);
            uint32_t a2 = __float_as_uint(Qw[g*68     + k0 + tig + 4]);
            uint32_t a3 = __float_as_uint(Qw[(g+8)*68 + k0 + tig + 4]);
#pragma unroll
            for (int ni = 0; ni < 8; ni++) {
                uint32_t b0 = __float_as_uint(Kt[(ni*8+g)*68 + k0 + tig]);
                uint32_t b1 = __float_as_uint(Kt[(ni*8+g)*68 + k0 + tig + 4]);
                mma_tf32(s[ni][0], s[ni][1], s[ni][2], s[ni][3], a0,a1,a2,a3, b0,b1);
            }
        }
        // scale + mask + row maxes (rows g, g+8)
        float mc0 = -INFINITY, mc1 = -INFINITY;
#pragma unroll
        for (int ni = 0; ni < 8; ni++) {
            int colb = kt*64 + ni*8 + 2*tig;
#pragma unroll
            for (int cc = 0; cc < 4; cc++) {
                float v = s[ni][cc] * 0.125f;
                if (colb + (cc & 1) >= N_) v = -INFINITY;
                s[ni][cc] = v;
                if (cc < 2) mc0 = fmaxf(mc0, v); else mc1 = fmaxf(mc1, v);
            }
        }
        mc0 = fmaxf(mc0, __shfl_xor_sync(~0u, mc0, 1));
        mc0 = fmaxf(mc0, __shfl_xor_sync(~0u, mc0, 2));
        mc1 = fmaxf(mc1, __shfl_xor_sync(~0u, mc1, 1));
        mc1 = fmaxf(mc1, __shfl_xor_sync(~0u, mc1, 2));
        float mn0 = fmaxf(mr0, mc0), mn1 = fmaxf(mr1, mc1);
        float al0 = expf(mr0 - mn0), al1 = expf(mr1 - mn1);
        mr0 = mn0; mr1 = mn1;
        float ls0 = 0.f, ls1 = 0.f;
#pragma unroll
        for (int ni = 0; ni < 8; ni++) {
            float p0 = expf(s[ni][0] - mn0);
            float p1 = expf(s[ni][1] - mn0);
            float p2 = expf(s[ni][2] - mn1);
            float p3 = expf(s[ni][3] - mn1);
            s[ni][0]=p0; s[ni][1]=p1; s[ni][2]=p2; s[ni][3]=p3;
            ls0 += p0 + p1; ls1 += p2 + p3;
        }
        ls0 += __shfl_xor_sync(~0u, ls0, 1); ls0 += __shfl_xor_sync(~0u, ls0, 2);
        ls1 += __shfl_xor_sync(~0u, ls1, 1); ls1 += __shfl_xor_sync(~0u, ls1, 2);
        l0 = l0*al0 + ls0; l1 = l1*al1 + ls1;

        __syncwarp();
#pragma unroll
        for (int ni = 0; ni < 8; ni++) {
            *(float2*)(Pw + g*68     + ni*8 + 2*tig) = make_float2(rndtf32(s[ni][0]), rndtf32(s[ni][1]));
            *(float2*)(Pw + (g+8)*68 + ni*8 + 2*tig) = make_float2(rndtf32(s[ni][2]), rndtf32(s[ni][3]));
        }
#pragma unroll
        for (int ni = 0; ni < 8; ni++) {
            o[ni][0]*=al0; o[ni][1]*=al0; o[ni][2]*=al1; o[ni][3]*=al1;
        }
        __syncwarp();
        // O += P V
#pragma unroll
        for (int ks = 0; ks < 8; ks++) {
            int k0 = ks*8;
            uint32_t a0 = __float_as_uint(Pw[g*68     + k0 + tig]);
            uint32_t a1 = __float_as_uint(Pw[(g+8)*68 + k0 + tig]);
            uint32_t a2 = __float_as_uint(Pw[g*68     + k0 + tig + 4]);
            uint32_t a3 = __float_as_uint(Pw[(g+8)*68 + k0 + tig + 4]);
#pragma unroll
            for (int ni = 0; ni < 8; ni++) {
                uint32_t b0 = __float_as_uint(Vt[(k0+tig)*72   + ni*8 + g]);
                uint32_t b1 = __float_as_uint(Vt[(k0+tig+4)*72 + ni*8 + g]);
                mma_tf32(o[ni][0], o[ni][1], o[ni][2], o[ni][3], a0,a1,a2,a3, b0,b1);
            }
        }
        __syncthreads();
        if (kt + 2 < 8) FA_ISSUE(kt + 2, buf);
    }
#undef FA_ISSUE

    int r0 = q0 + warp*16 + g, r1 = r0 + 8;
    float inv0 = 1.f / l0, inv1 = 1.f / l1;
#pragma unroll
    for (int ni = 0; ni < 8; ni++) {
        int col = h*D_ + ni*8 + 2*tig;
        if (r0 < N_)
            *(float2*)(obuf + ((size_t)b*N_ + r0)*C_ + col) =
                make_float2(rndtf32(o[ni][0]*inv0), rndtf32(o[ni][1]*inv0));
        if (r1 < N_)
            *(float2*)(obuf + ((size_t)b*N_ + r1)*C_ + col) =
                make_float2(rndtf32(o[ni][2]*inv1), rndtf32(o[ni][3]*inv1));
    }
}

// ---------------- cls attention row (exact fp32 softmax of q-row 0) ----------------
__global__ __launch_bounds__(256)
void cls_kernel(const float* __restrict__ qkv, float* __restrict__ cls_acc) {
    __shared__ float q0s[64];
    __shared__ float red[8];
    int bh = blockIdx.x;
    int b = bh / H_, h = bh % H_;
    const float* base = qkv + (size_t)b * N_ * (3*C_) + h * D_;
    int tid = threadIdx.x, lane = tid & 31, warp = tid >> 5;
    if (tid < 64) q0s[tid] = base[tid];
    __syncthreads();

    float s0 = -INFINITY, s1 = -INFINITY;
    {
        int j = tid;
        if (j < N_) {
            float a = 0.f;
            const float* k = base + (size_t)j*(3*C_) + C_;
#pragma unroll 16
            for (int d = 0; d < 64; d++) a += q0s[d]*k[d];
            s0 = a * 0.125f;
        }
        j = tid + 256;
        if (j < N_) {
            float a = 0.f;
            const float* k = base + (size_t)j*(3*C_) + C_;
#pragma unroll 16
            for (int d = 0; d < 64; d++) a += q0s[d]*k[d];
            s1 = a * 0.125f;
        }
    }
    float m = fmaxf(s0, s1);
#pragma unroll
    for (int off = 16; off; off >>= 1) m = fmaxf(m, __shfl_xor_sync(~0u, m, off));
    if (lane == 0) red[warp] = m;
    __syncthreads();
    float M = red[0];
#pragma unroll
    for (int i = 1; i < 8; i++) M = fmaxf(M, red[i]);
    __syncthreads();
    float e0 = expf(s0 - M), e1 = expf(s1 - M);
    float t = e0 + e1;
#pragma unroll
    for (int off = 16; off; off >>= 1) t += __shfl_xor_sync(~0u, t, off);
    if (lane == 0) red[warp] = t;
    __syncthreads();
    float L = 0.f;
#pragma unroll
    for (int i = 0; i < 8; i++) L += red[i];
    float invL = 1.f / (L * (float)H_);
    int j = tid;
    if (j >= 1 && j < N_) atomicAdd(&cls_acc[b*(N_-1) + j - 1], e0 * invL);
    j = tid + 256;
    if (j < N_) atomicAdd(&cls_acc[b*(N_-1) + j - 1], e1 * invL);
}

// ---------------- glb EMA ----------------
__global__ void glb_kernel() {
    int i = blockIdx.x*blockDim.x + threadIdx.x;
    if (i < B_*(N_-1)) {
        g_glb[i] = 0.5f * g_glb[i] + 0.5f * g_cls[i];
        g_cls[i] = 0.f;
    }
}

// ---------------- output ----------------
__global__ void copy_out_kernel(float* __restrict__ out, int out_size) {
    const int NX = B_*N_*C_;
    const int NG = B_*(N_-1);
    for (int i = blockIdx.x*blockDim.x + threadIdx.x; i < out_size;
         i += gridDim.x*blockDim.x) {
        float v = 0.f;
        if (i < NX)            v = g_x[i];
        else if (i < NX + NG)  v = g_glb[i - NX];
        out[i] = v;
    }
}

// ---------------- launch ----------------
extern "C" void kernel_launch(void* const* d_in, const int* in_sizes, int n_in,
                              void* d_out, int out_size) {
    const float* x       = (const float*)d_in[0];
    const float* gattn   = (const float*)d_in[1];
    const float* split_w = (const float*)d_in[2];
    const float* split_b = (const float*)d_in[3];
    const float* ln1_g   = (const float*)d_in[4];
    const float* ln1_b   = (const float*)d_in[5];
    const float* qkv_w   = (const float*)d_in[6];
    const float* qkv_b   = (const float*)d_in[7];
    const float* proj_w  = (const float*)d_in[8];
    const float* proj_b  = (const float*)d_in[9];
    const float* ln2_g   = (const float*)d_in[10];
    const float* ln2_b   = (const float*)d_in[11];
    const float* fc1_w   = (const float*)d_in[12];
    const float* fc1_b   = (const float*)d_in[13];
    const float* fc2_w   = (const float*)d_in[14];
    const float* fc2_b   = (const float*)d_in[15];

    float *px, *ph, *pqkv, *po, *pmlp, *ptok, *pcls;
    float *pwsplit, *pwqkv, *pwproj, *pwfc1, *pwfc2;
    cudaGetSymbolAddress((void**)&px,   g_x);
    cudaGetSymbolAddress((void**)&ph,   g_h);
    cudaGetSymbolAddress((void**)&pqkv, g_qkv);
    cudaGetSymbolAddress((void**)&po,   g_o);
    cudaGetSymbolAddress((void**)&pmlp, g_mlp);
    cudaGetSymbolAddress((void**)&ptok, g_tok);
    cudaGetSymbolAddress((void**)&pcls, g_cls);
    cudaGetSymbolAddress((void**)&pwsplit, g_wsplit);
    cudaGetSymbolAddress((void**)&pwqkv,   g_wqkv);
    cudaGetSymbolAddress((void**)&pwproj,  g_wproj);
    cudaGetSymbolAddress((void**)&pwfc1,   g_wfc1);
    cudaGetSymbolAddress((void**)&pwfc2,   g_wfc2);

    cudaFuncSetAttribute(gemm_cp,    cudaFuncAttributeMaxDynamicSharedMemorySize, GEMM_SMEM);
    cudaFuncSetAttribute(flash_attn, cudaFuncAttributeMaxDynamicSharedMemorySize, FA_SMEM);

    wconv_kernel<<<2048, 256>>>(split_w, pwsplit, SW_SZ);
    wconv_kernel<<<2048, 256>>>(qkv_w,   pwqkv,   L_*QW_SZ);
    wconv_kernel<<<2048, 256>>>(proj_w,  pwproj,  L_*PW_SZ);
    wconv_kernel<<<2048, 256>>>(fc1_w,   pwfc1,   L_*F1_SZ);
    wconv_kernel<<<2048, 256>>>(fc2_w,   pwfc2,   L_*F2_SZ);

    sort_kernel<<<B_, 256>>>(gattn);
    gather_kernel<<<B_*197, 256>>>(x);
    init_kernel<<<(B_*(N_-1) + 255)/256, 256>>>();

    {
        int M = B_*SPLN, N = 4*C_, K = C_;
        dim3 grid(N/128, (M + 127)/128);
        gemm_cp<<<grid, 256, GEMM_SMEM>>>(ptok, pwsplit, split_b, nullptr, px, M, N, K, 3);
    }

    for (int l = 0; l < L_; l++) {
        const float* l1g = ln1_g + l*C_;
        const float* l1b = ln1_b + l*C_;
        const float* qw  = pwqkv + (size_t)l*QW_SZ;
        const float* qb  = qkv_b + l*3*C_;
        const float* pw  = pwproj + (size_t)l*PW_SZ;
        const float* pb  = proj_b + l*C_;
        const float* l2g = ln2_g + l*C_;
        const float* l2b = ln2_b + l*C_;
        const float* w1  = pwfc1 + (size_t)l*F1_SZ;
        const float* b1  = fc1_b + l*HM_;
        const float* w2  = pwfc2 + (size_t)l*F2_SZ;
        const float* b2  = fc2_b + l*C_;

        ln_kernel<<<M_ROWS, 256>>>(px, ph, l1g, l1b);

        { dim3 grid((3*C_)/128, (M_ROWS + 127)/128);
          gemm_cp<<<grid, 256, GEMM_SMEM>>>(ph, qw, qb, nullptr, pqkv, M_ROWS, 3*C_, C_, 0); }

        cls_kernel<<<B_*H_, 256>>>(pqkv, pcls);

        { dim3 grid(4, B_*H_);
          flash_attn<<<grid, 256, FA_SMEM>>>(pqkv, po); }

        glb_kernel<<<(B_*(N_-1) + 255)/256, 256>>>();

        { dim3 grid(C_/128, (M_ROWS + 127)/128);
          gemm_cp<<<grid, 256, GEMM_SMEM>>>(po, pw, pb, px, px, M_ROWS, C_, C_, 2); }

        ln_kernel<<<M_ROWS, 256>>>(px, ph, l2g, l2b);

        { dim3 grid(HM_/128, (M_ROWS + 127)/128);
          gemm_cp<<<grid, 256, GEMM_SMEM>>>(ph, w1, b1, nullptr, pmlp, M_ROWS, HM_, C_, 1); }

        { dim3 grid(C_/128, (M_ROWS + 127)/128);
          gemm_cp<<<grid, 256, GEMM_SMEM>>>(pmlp, w2, b2, px, px, M_ROWS, C_, HM_, 2); }
    }

    copy_out_kernel<<<2048, 256>>>((float*)d_out, out_size);
}